// round 5
// baseline (speedup 1.0000x reference)
#include <cuda_runtime.h>
#include <math.h>

#define NB 16
#define CCH 512

// Layer output lengths (VALID conv): floor((L-k)/s)+1
#define T0 6399   // 32000, k10 s5
#define T1 1598   // k8 s4
#define T2 798    // k4 s2
#define T3 398
#define T4 198

// ---------------- pooled scratch (single static device allocation) ----------------
#define P0_ELEMS ((size_t)NB * CCH * T0)
#define P1_ELEMS ((size_t)NB * CCH * T1)
#define F_ELEMS  ((size_t)NB * CCH * T4)
#define C_ELEMS  ((size_t)NB * 512 * 512)

#define OFF_P0  ((size_t)0)
#define OFF_P1  (OFF_P0 + P0_ELEMS + 4096)
#define OFF_FX  (OFF_P1 + P1_ELEMS + 4096)
#define OFF_FY  (OFF_FX + F_ELEMS)
#define OFF_SX  (OFF_FY + F_ELEMS)
#define OFF_SY  (OFF_SX + NB * CCH)
#define POOL_TOTAL (OFF_SY + NB * CCH + 4096)

#define OFF_CXY (OFF_P0)
#define OFF_CYX (OFF_CXY + C_ELEMS)
#define OFF_CXX (OFF_CYX + C_ELEMS)
#define OFF_CYY (OFF_CXX + C_ELEMS)

__device__ float  d_pool[POOL_TOTAL];
__device__ float  d_Wt1[4096 * 512];
__device__ float  d_Wt2[2048 * 512];
__device__ float  d_Wt3[2048 * 512];
__device__ float  d_Wt4[2048 * 512];
__device__ double d_stats[2 * NB];
__device__ float2 d_murs[NB];
__device__ float  d_w[3 * NB];

// ---------------- conv layer 0 (cin = 1, k=10, s=5) ----------------
__global__ void conv0_k(const float* __restrict__ wav, const float* __restrict__ W0,
                        float* __restrict__ out) {
    __shared__ float Ws[5120];
    int tid = threadIdx.x;  // 128
    for (int e = tid; e < 5120; e += 128) Ws[e] = W0[e];
    __syncthreads();
    int b = blockIdx.y;
    int t = blockIdx.x * 128 + tid;
    if (t >= T0) return;
    float w[10];
    const float* wp = wav + (size_t)b * 32000 + t * 5;
#pragma unroll
    for (int j = 0; j < 10; j++) w[j] = wp[j];
    float* op = out + (size_t)b * CCH * T0 + t;
    for (int co = 0; co < 512; co++) {
        float acc = 0.f;
#pragma unroll
        for (int j = 0; j < 10; j++) acc = fmaf(Ws[co * 10 + j], w[j], acc);
        op[(size_t)co * T0] = acc;
    }
}

// ---------------- weight transpose: W[co][ci][j] -> Wt[kk][co] ----------------
__global__ void transpose_k(const float* __restrict__ W, float* __restrict__ Wt, int K) {
    int idx = blockIdx.x * 256 + threadIdx.x;
    if (idx >= K * 512) return;
    int co = idx & 511, kk = idx >> 9;
    Wt[idx] = W[co * K + kk];
}

// ---------------- generic conv as implicit-im2col SGEMM ----------------
template <int KW, int SS, int CICH>
__global__ __launch_bounds__(256) void conv_gemm(const float* __restrict__ in,
                                                 const float* __restrict__ wt,
                                                 float* __restrict__ out,
                                                 int Tin, int Tout) {
    constexpr int SPAN = 127 * SS + KW;
    constexpr int KK = CICH * KW;  // 32
    __shared__ float Ws[KK][128];
    __shared__ float Is[CICH][SPAN];
    int tid = threadIdx.x;
    int tx = tid & 15, ty = tid >> 4;
    int b = blockIdx.z;
    int coBase = blockIdx.y * 128;
    int t0 = blockIdx.x * 128;
    const float* inB = in + (size_t)b * 512 * Tin;
    int tIn0 = t0 * SS;
    float acc[8][8];
#pragma unroll
    for (int v = 0; v < 8; v++)
#pragma unroll
        for (int u = 0; u < 8; u++) acc[v][u] = 0.f;

    for (int ci0 = 0; ci0 < 512; ci0 += CICH) {
#pragma unroll
        for (int q = 0; q < KK * 128 / 256; q++) {
            int e = tid + q * 256;
            int r = e >> 7, c = e & 127;
            Ws[r][c] = wt[(ci0 * KW + r) * 512 + coBase + c];
        }
        for (int e = tid; e < CICH * SPAN; e += 256) {
            int ci = e / SPAN, col = e - ci * SPAN;
            Is[ci][col] = inB[(size_t)(ci0 + ci) * Tin + tIn0 + col];
        }
        __syncthreads();
#pragma unroll
        for (int ci = 0; ci < CICH; ci++) {
#pragma unroll
            for (int j = 0; j < KW; j++) {
                float a[8], bb[8];
#pragma unroll
                for (int v = 0; v < 8; v++) a[v] = Ws[ci * KW + j][ty + 16 * v];
#pragma unroll
                for (int u = 0; u < 8; u++) bb[u] = Is[ci][(tx + 16 * u) * SS + j];
#pragma unroll
                for (int v = 0; v < 8; v++)
#pragma unroll
                    for (int u = 0; u < 8; u++) acc[v][u] = fmaf(a[v], bb[u], acc[v][u]);
            }
        }
        __syncthreads();
    }
    float* outB = out + (size_t)b * 512 * Tout;
#pragma unroll
    for (int v = 0; v < 8; v++) {
        int co = coBase + ty + 16 * v;
#pragma unroll
        for (int u = 0; u < 8; u++) {
            int t = t0 + tx + 16 * u;
            if (t < Tout) outB[(size_t)co * Tout + t] = acc[v][u];
        }
    }
}

// ---------------- group-norm stats (sum, sumsq per batch, double) ----------------
__global__ void zero_stats_k(double* stats) {
    if (threadIdx.x < 32) stats[threadIdx.x] = 0.0;
}

__global__ void stats_k(const float* __restrict__ in, double* stats, int L) {
    __shared__ double s1[256], s2[256];
    int b = blockIdx.x;
    int cs = (L + gridDim.y - 1) / gridDim.y;
    int start = blockIdx.y * cs;
    int end = min(L, start + cs);
    const float* p = in + (size_t)b * L;
    double s = 0.0, q = 0.0;
    for (int i = start + threadIdx.x; i < end; i += 256) {
        double v = (double)p[i];
        s += v;
        q += v * v;
    }
    s1[threadIdx.x] = s;
    s2[threadIdx.x] = q;
    __syncthreads();
    for (int st = 128; st > 0; st >>= 1) {
        if (threadIdx.x < st) {
            s1[threadIdx.x] += s1[threadIdx.x + st];
            s2[threadIdx.x] += s2[threadIdx.x + st];
        }
        __syncthreads();
    }
    if (threadIdx.x == 0) {
        atomicAdd(&stats[2 * b], s1[0]);
        atomicAdd(&stats[2 * b + 1], s2[0]);
    }
}

__global__ void statsfin_k(const double* stats, float2* murs, int L) {
    int i = threadIdx.x;
    if (i < NB) {
        double mu = stats[2 * i] / (double)L;
        double var = stats[2 * i + 1] / (double)L - mu * mu;
        double rs = 1.0 / sqrt(var + 1e-5);
        murs[i] = make_float2((float)mu, (float)rs);
    }
}

__global__ void norm_k(float* __restrict__ buf, float* __restrict__ outp,
                       const float* __restrict__ g, const float* __restrict__ be,
                       const float2* __restrict__ murs, int T) {
    long long total = (long long)NB * CCH * T;
    long long idx = (long long)blockIdx.x * 256 + threadIdx.x;
    if (idx >= total) return;
    int b = (int)(idx / ((long long)CCH * T));
    int c = (int)((idx / T) % CCH);
    float2 mr = murs[b];
    float v = (buf[idx] - mr.x) * mr.y * g[c] + be[c];
    outp[idx] = fmaxf(v, 0.f);
}

// ---------------- feature squared norms ----------------
__global__ void sqnorm_k(const float* __restrict__ f, float* __restrict__ s) {
    int idx = blockIdx.x * 256 + threadIdx.x;
    if (idx >= NB * CCH) return;
    const float* p = f + (size_t)idx * T4;
    float acc = 0.f;
    for (int d = 0; d < T4; d++) acc = fmaf(p[d], p[d], acc);
    s[idx] = acc;
}

// ---------------- cost matrix ----------------
__global__ __launch_bounds__(256) void cost_k(const float* __restrict__ A,
                                              const float* __restrict__ Bf,
                                              const float* __restrict__ sa,
                                              const float* __restrict__ sb,
                                              float* __restrict__ Co) {
    __shared__ float As[64][17], Bs[64][17];
    int b = blockIdx.z;
    const float* Ab = A + (size_t)b * 512 * T4;
    const float* Bb = Bf + (size_t)b * 512 * T4;
    int n0 = blockIdx.y * 64, m0 = blockIdx.x * 64;
    int tid = threadIdx.x;
    int rn = tid >> 4, cm = tid & 15;
    float acc[4][4];
#pragma unroll
    for (int i = 0; i < 4; i++)
#pragma unroll
        for (int j = 0; j < 4; j++) acc[i][j] = 0.f;
    for (int d0 = 0; d0 < T4; d0 += 16) {
#pragma unroll
        for (int q = 0; q < 4; q++) {
            int e = tid + q * 256;
            int r = e >> 4, dd = e & 15;
            As[r][dd] = (d0 + dd < T4) ? Ab[(size_t)(n0 + r) * T4 + d0 + dd] : 0.f;
            Bs[r][dd] = (d0 + dd < T4) ? Bb[(size_t)(m0 + r) * T4 + d0 + dd] : 0.f;
        }
        __syncthreads();
#pragma unroll
        for (int dd = 0; dd < 16; dd++) {
            float a[4], bb[4];
#pragma unroll
            for (int i = 0; i < 4; i++) a[i] = As[rn * 4 + i][dd];
#pragma unroll
            for (int j = 0; j < 4; j++) bb[j] = Bs[cm * 4 + j][dd];
#pragma unroll
            for (int i = 0; i < 4; i++)
#pragma unroll
                for (int j = 0; j < 4; j++) acc[i][j] = fmaf(a[i], bb[j], acc[i][j]);
        }
        __syncthreads();
    }
    const float* sab = sa + b * 512;
    const float* sbb = sb + b * 512;
    float* Cb = Co + (size_t)b * 512 * 512;
#pragma unroll
    for (int i = 0; i < 4; i++) {
        int n = n0 + rn * 4 + i;
#pragma unroll
        for (int j = 0; j < 4; j++) {
            int m = m0 + cm * 4 + j;
            Cb[(size_t)n * 512 + m] = 0.5f * fmaxf(sab[n] + sbb[m] - 2.f * acc[i][j], 0.f);
        }
    }
}

// ---------------- sinkhorn (log-domain, 50 iters) ----------------
__global__ __launch_bounds__(512) void sinkhorn_k(const float* __restrict__ Cxy,
                                                  const float* __restrict__ Cyx,
                                                  const float* __restrict__ Cxx,
                                                  const float* __restrict__ Cyy,
                                                  float* __restrict__ w) {
    __shared__ float fs[512], gs[512];
    int b = blockIdx.x, ot = blockIdx.y;
    size_t off = (size_t)b * 512 * 512;
    const float *Cg, *Cf;
    if (ot == 0) { Cg = Cxy + off; Cf = Cyx + off; }
    else if (ot == 1) { Cg = Cxx + off; Cf = Cg; }
    else { Cg = Cyy + off; Cf = Cg; }
    int tid = threadIdx.x;
    fs[tid] = 0.f;
    gs[tid] = 0.f;
    __syncthreads();
    const float LA = -6.2383246250395075f;  // -log(512)
    const float EPS = 0.0025f, IEPS = 400.f;
    for (int it = 0; it < 50; it++) {
        {
            const float* cp = Cg + tid;
            float M = -3.4e38f;
            for (int n = 0; n < 512; n += 8) {
                float v[8];
#pragma unroll
                for (int i = 0; i < 8; i++) v[i] = fs[n + i] - cp[(size_t)(n + i) << 9];
#pragma unroll
                for (int i = 0; i < 8; i++) M = fmaxf(M, v[i]);
            }
            float S = 0.f;
            for (int n = 0; n < 512; n += 8) {
                float v[8];
#pragma unroll
                for (int i = 0; i < 8; i++) v[i] = fs[n + i] - cp[(size_t)(n + i) << 9];
#pragma unroll
                for (int i = 0; i < 8; i++) S += __expf((v[i] - M) * IEPS);
            }
            gs[tid] = -EPS * (LA + __logf(S)) - M;
        }
        __syncthreads();
        {
            const float* cp = Cf + tid;
            float M = -3.4e38f;
            for (int m = 0; m < 512; m += 8) {
                float v[8];
#pragma unroll
                for (int i = 0; i < 8; i++) v[i] = gs[m + i] - cp[(size_t)(m + i) << 9];
#pragma unroll
                for (int i = 0; i < 8; i++) M = fmaxf(M, v[i]);
            }
            float S = 0.f;
            for (int m = 0; m < 512; m += 8) {
                float v[8];
#pragma unroll
                for (int i = 0; i < 8; i++) v[i] = gs[m + i] - cp[(size_t)(m + i) << 9];
#pragma unroll
                for (int i = 0; i < 8; i++) S += __expf((v[i] - M) * IEPS);
            }
            fs[tid] = -EPS * (LA + __logf(S)) - M;
        }
        __syncthreads();
    }
    fs[tid] += gs[tid];
    __syncthreads();
    for (int s = 256; s > 0; s >>= 1) {
        if (tid < s) fs[tid] += fs[tid + s];
        __syncthreads();
    }
    if (tid == 0) w[ot * 16 + b] = fs[0] * (1.f / 512.f);
}

__global__ void final_k(const float* __restrict__ w, float* __restrict__ out) {
    int b = threadIdx.x;
    if (b < NB) out[b] = w[b] - 0.5f * (w[16 + b] + w[32 + b]);
}

// ---------------- host driver ----------------
static void normseq(float* buf, int T, const float* g, const float* be, float* outp,
                    double* statsp, float2* mursp) {
    zero_stats_k<<<1, 32>>>(statsp);
    int L = CCH * T;
    stats_k<<<dim3(16, 48), 256>>>(buf, statsp, L);
    statsfin_k<<<1, 32>>>(statsp, mursp, L);
    long long total = (long long)NB * CCH * T;
    norm_k<<<(unsigned)((total + 255) / 256), 256>>>(buf, outp, g, be, mursp, T);
}

extern "C" void kernel_launch(void* const* d_in, const int* in_sizes, int n_in,
                              void* d_out, int out_size) {
    (void)out_size;
    const float* y_hat = (const float*)d_in[0];
    const float* y     = (const float*)d_in[1];
    const float* W[5];
    const float* g[5];
    const float* be[5];

    // Input layout detection:
    //   setup_inputs() dict order (interleaved): y_hat, y, W0,g0,b0, W1,g1,b1, ...
    //     -> in_sizes[3] == 512
    //   reference-signature order (flat): y_hat, y, W0..W4, g0..g4, b0..b4
    //     -> in_sizes[3] > 1024 (W1 = 512*512*8)
    if (n_in >= 17 && in_sizes[3] <= 1024) {
        for (int i = 0; i < 5; i++) {
            W[i]  = (const float*)d_in[2 + 3 * i];
            g[i]  = (const float*)d_in[3 + 3 * i];
            be[i] = (const float*)d_in[4 + 3 * i];
        }
    } else {
        for (int i = 0; i < 5; i++) {
            W[i]  = (const float*)d_in[2 + i];
            g[i]  = (const float*)d_in[7 + i];
            be[i] = (const float*)d_in[12 + i];
        }
    }
    float* out = (float*)d_out;

    float *pool, *Wt1, *Wt2, *Wt3, *Wt4, *wv;
    double* stats;
    float2* murs;
    cudaGetSymbolAddress((void**)&pool, d_pool);
    cudaGetSymbolAddress((void**)&Wt1, d_Wt1);
    cudaGetSymbolAddress((void**)&Wt2, d_Wt2);
    cudaGetSymbolAddress((void**)&Wt3, d_Wt3);
    cudaGetSymbolAddress((void**)&Wt4, d_Wt4);
    cudaGetSymbolAddress((void**)&stats, d_stats);
    cudaGetSymbolAddress((void**)&murs, d_murs);
    cudaGetSymbolAddress((void**)&wv, d_w);

    float* P0  = pool + OFF_P0;
    float* P1  = pool + OFF_P1;
    float* fx  = pool + OFF_FX;
    float* fy  = pool + OFF_FY;
    float* sx  = pool + OFF_SX;
    float* sy  = pool + OFF_SY;
    float* Cxy = pool + OFF_CXY;
    float* Cyx = pool + OFF_CYX;
    float* Cxx = pool + OFF_CXX;
    float* Cyy = pool + OFF_CYY;

    transpose_k<<<4096 * 512 / 256, 256>>>(W[1], Wt1, 4096);
    transpose_k<<<2048 * 512 / 256, 256>>>(W[2], Wt2, 2048);
    transpose_k<<<2048 * 512 / 256, 256>>>(W[3], Wt3, 2048);
    transpose_k<<<2048 * 512 / 256, 256>>>(W[4], Wt4, 2048);

    for (int s = 0; s < 2; s++) {
        const float* wav = s ? y : y_hat;
        float* feat = s ? fy : fx;
        conv0_k<<<dim3((T0 + 127) / 128, NB), 128>>>(wav, W[0], P0);
        normseq(P0, T0, g[0], be[0], P0, stats, murs);
        conv_gemm<8, 4, 4><<<dim3((T1 + 127) / 128, 4, NB), 256>>>(P0, Wt1, P1, T0, T1);
        normseq(P1, T1, g[1], be[1], P1, stats, murs);
        conv_gemm<4, 2, 8><<<dim3((T2 + 127) / 128, 4, NB), 256>>>(P1, Wt2, P0, T1, T2);
        normseq(P0, T2, g[2], be[2], P0, stats, murs);
        conv_gemm<4, 2, 8><<<dim3((T3 + 127) / 128, 4, NB), 256>>>(P0, Wt3, P1, T2, T3);
        normseq(P1, T3, g[3], be[3], P1, stats, murs);
        conv_gemm<4, 2, 8><<<dim3((T4 + 127) / 128, 4, NB), 256>>>(P1, Wt4, P0, T3, T4);
        normseq(P0, T4, g[4], be[4], feat, stats, murs);
    }

    sqnorm_k<<<(NB * CCH + 255) / 256, 256>>>(fx, sx);
    sqnorm_k<<<(NB * CCH + 255) / 256, 256>>>(fy, sy);

    cost_k<<<dim3(8, 8, NB), 256>>>(fx, fy, sx, sy, Cxy);
    cost_k<<<dim3(8, 8, NB), 256>>>(fy, fx, sy, sx, Cyx);
    cost_k<<<dim3(8, 8, NB), 256>>>(fx, fx, sx, sx, Cxx);
    cost_k<<<dim3(8, 8, NB), 256>>>(fy, fy, sy, sy, Cyy);

    sinkhorn_k<<<dim3(NB, 3), 512>>>(Cxy, Cyx, Cxx, Cyy, wv);
    final_k<<<1, 32>>>(wv, out);
}

// round 9
// speedup vs baseline: 1.7455x; 1.7455x over previous
#include <cuda_runtime.h>
#include <cuda_bf16.h>
#include <mma.h>
#include <math.h>
#include <stdint.h>

using namespace nvcuda;

#define NB 16
#define CCH 512
#define T0 6399
#define T1 1598
#define T2 798
#define T3 398
#define T4 198
#define T0P 6400
// padded output strides (= ceil(T/128)*128)
#define O1P 1664
#define O2P 896
#define O3P 512
#define O4P 256

#define PL_ELEMS  ((size_t)NB * 512 * T0P)         // floats; holds hi+lo ushort planes
#define OUT_ELEMS ((size_t)NB * 512 * O1P)
#define F_ELEMS   ((size_t)NB * 512 * T4)
#define C_ELEMS   ((size_t)NB * 512 * 512)
#define OFF_PL   ((size_t)0)
#define OFF_OUT  (OFF_PL + PL_ELEMS + 1024)
#define OFF_FX   (OFF_OUT + OUT_ELEMS + 1024)
#define OFF_FY   (OFF_FX + F_ELEMS)
#define OFF_SX   (OFF_FY + F_ELEMS)
#define OFF_SY   (OFF_SX + NB * CCH)
#define POOL_TOTAL (OFF_SY + NB * CCH + 1024)
#define OFF_CXY  (OFF_PL)
#define OFF_CYX  (OFF_CXY + C_ELEMS)
#define OFF_CXX  (OFF_CYX + C_ELEMS)
#define OFF_CYY  (OFF_CXX + C_ELEMS)

__device__ float d_pool[POOL_TOTAL];
// weight bf16 hi/lo planes: W1h,W1l (512*4096 each), W2h,W2l,W3h,W3l,W4h,W4l (512*2048 each)
__device__ unsigned short d_WB[2 * 512 * 4096 + 6 * 512 * 2048];
__device__ double d_stats[2 * NB];
__device__ float2 d_murs[NB];
__device__ float d_w[3 * NB];
#define W1H ((size_t)0)
#define W1L (W1H + (size_t)512 * 4096)
#define W2H (W1L + (size_t)512 * 4096)
#define W2L (W2H + (size_t)512 * 2048)
#define W3H (W2L + (size_t)512 * 2048)
#define W3L (W3H + (size_t)512 * 2048)
#define W4H (W3L + (size_t)512 * 2048)
#define W4L (W4H + (size_t)512 * 2048)

// ---- weight split into bf16 hi/lo planes ----
__global__ void packW_k(const float* __restrict__ W, unsigned short* __restrict__ Wh,
                        unsigned short* __restrict__ Wl, int n) {
    int e = blockIdx.x * 256 + threadIdx.x;
    if (e >= n) return;
    float x = W[e];
    __nv_bfloat16 h = __float2bfloat16(x);
    __nv_bfloat16 l = __float2bfloat16(x - __bfloat162float(h));
    Wh[e] = __bfloat16_as_ushort(h);
    Wl[e] = __bfloat16_as_ushort(l);
}

// ---- conv0 (cin=1,k=10,s=5): stats pass + fused norm/pack pass ----
__global__ void conv0_stats_k(const float* __restrict__ wav, const float* __restrict__ W0,
                              double* stats) {
    __shared__ float Ws[5120];
    __shared__ double r1[128], r2[128];
    int tid = threadIdx.x;
    for (int e = tid; e < 5120; e += 128) Ws[e] = W0[e];
    __syncthreads();
    int b = blockIdx.y, t = blockIdx.x * 128 + tid;
    double s = 0.0, q = 0.0;
    if (t < T0) {
        float w[10];
        const float* wp = wav + (size_t)b * 32000 + t * 5;
#pragma unroll
        for (int j = 0; j < 10; j++) w[j] = wp[j];
        for (int co = 0; co < 512; co++) {
            float a = 0.f;
#pragma unroll
            for (int j = 0; j < 10; j++) a = fmaf(Ws[co * 10 + j], w[j], a);
            s += a; q += (double)a * a;
        }
    }
    r1[tid] = s; r2[tid] = q;
    __syncthreads();
    for (int st = 64; st > 0; st >>= 1) {
        if (tid < st) { r1[tid] += r1[tid + st]; r2[tid] += r2[tid + st]; }
        __syncthreads();
    }
    if (tid == 0) { atomicAdd(&stats[2 * b], r1[0]); atomicAdd(&stats[2 * b + 1], r2[0]); }
}

__global__ void conv0_pack_k(const float* __restrict__ wav, const float* __restrict__ W0,
                             const float* __restrict__ g, const float* __restrict__ be,
                             const float2* __restrict__ murs,
                             unsigned short* __restrict__ hip, unsigned short* __restrict__ lop) {
    __shared__ float Ws[5120], gS[512], bS[512];
    int tid = threadIdx.x;
    for (int e = tid; e < 5120; e += 128) Ws[e] = W0[e];
    for (int e = tid; e < 512; e += 128) { gS[e] = g[e]; bS[e] = be[e]; }
    __syncthreads();
    int b = blockIdx.y, t = blockIdx.x * 128 + tid;
    if (t >= T0) return;
    float2 mr = murs[b];
    float w[10];
    const float* wp = wav + (size_t)b * 32000 + t * 5;
#pragma unroll
    for (int j = 0; j < 10; j++) w[j] = wp[j];
    size_t base = (size_t)b * 512 * T0P + t;
    for (int co = 0; co < 512; co++) {
        float a = 0.f;
#pragma unroll
        for (int j = 0; j < 10; j++) a = fmaf(Ws[co * 10 + j], w[j], a);
        float v = fmaxf((a - mr.x) * mr.y * gS[co] + bS[co], 0.f);
        __nv_bfloat16 h = __float2bfloat16(v);
        __nv_bfloat16 l = __float2bfloat16(v - __bfloat162float(h));
        hip[base + (size_t)co * T0P] = __bfloat16_as_ushort(h);
        lop[base + (size_t)co * T0P] = __bfloat16_as_ushort(l);
    }
}

// ---- WMMA conv GEMM: 128co x 128t tile, K chunk 64, bf16 hi/lo 3-pass ----
template <int KW, int SS>
__global__ __launch_bounds__(256) void conv_wmma(
    const unsigned short* __restrict__ hiP, const unsigned short* __restrict__ loP,
    const unsigned short* __restrict__ Whp, const unsigned short* __restrict__ Wlp,
    float* __restrict__ out, int TPin, int OUTP, int Tout, int K) {
    extern __shared__ char smem[];
    __nv_bfloat16* Ah = (__nv_bfloat16*)smem;     // [128][72] row=co col=k
    __nv_bfloat16* Al = Ah + 128 * 72;
    __nv_bfloat16* Bh = Al + 128 * 72;            // [128][72] row=t col=k (B col-major)
    __nv_bfloat16* Bl = Bh + 128 * 72;
    int tid = threadIdx.x, wid = tid >> 5;
    int wc = wid & 3, wt = wid >> 2;
    int t0 = blockIdx.x * 128, co0 = blockIdx.y * 128, b = blockIdx.z;

    wmma::fragment<wmma::accumulator, 16, 16, 16, float> c[2][4];
#pragma unroll
    for (int i = 0; i < 2; i++)
#pragma unroll
        for (int j = 0; j < 4; j++) wmma::fill_fragment(c[i][j], 0.0f);

    const unsigned short* hB = hiP + (size_t)b * 512 * TPin;
    const unsigned short* lB = loP + (size_t)b * 512 * TPin;
    int KC = K >> 6;

    for (int ch = 0; ch < KC; ch++) {
        int kb = ch << 6;
        {   // A fill: 128 rows x 64 cols x 2 planes
            int row = tid >> 1, seg = tid & 1;
            const uint4* gh = (const uint4*)(Whp + (size_t)(co0 + row) * K + kb + seg * 32);
            const uint4* gl = (const uint4*)(Wlp + (size_t)(co0 + row) * K + kb + seg * 32);
            uint4* dh = (uint4*)(Ah + row * 72 + seg * 32);
            uint4* dl = (uint4*)(Al + row * 72 + seg * 32);
#pragma unroll
            for (int q = 0; q < 4; q++) { dh[q] = gh[q]; dl[q] = gl[q]; }
        }
        if (KW == 8) {
#pragma unroll
            for (int r = 0; r < 4; r++) {
                int e = r * 256 + tid;
                int t = e & 127, ci = e >> 7;  // ci 0..7
                int tt = t0 + t; if (tt > Tout - 1) tt = Tout - 1;
                size_t s = (size_t)((kb >> 3) + ci) * TPin + (size_t)tt * SS;
                uint2 h0 = *(const uint2*)(hB + s);
                uint2 h1 = *(const uint2*)(hB + s + 4);
                uint2 l0 = *(const uint2*)(lB + s);
                uint2 l1 = *(const uint2*)(lB + s + 4);
                *(uint4*)(Bh + t * 72 + ci * 8) = make_uint4(h0.x, h0.y, h1.x, h1.y);
                *(uint4*)(Bl + t * 72 + ci * 8) = make_uint4(l0.x, l0.y, l1.x, l1.y);
            }
        } else {
#pragma unroll
            for (int r = 0; r < 8; r++) {
                int e = r * 256 + tid;
                int t = e & 127, ci = e >> 7;  // ci 0..15
                int tt = t0 + t; if (tt > Tout - 1) tt = Tout - 1;
                size_t s = (size_t)((kb >> 2) + ci) * TPin + (size_t)tt * SS;
                uint32_t h0 = *(const uint32_t*)(hB + s);
                uint32_t h1 = *(const uint32_t*)(hB + s + 2);
                uint32_t l0 = *(const uint32_t*)(lB + s);
                uint32_t l1 = *(const uint32_t*)(lB + s + 2);
                *(uint2*)(Bh + t * 72 + ci * 4) = make_uint2(h0, h1);
                *(uint2*)(Bl + t * 72 + ci * 4) = make_uint2(l0, l1);
            }
        }
        __syncthreads();
#pragma unroll
        for (int kk = 0; kk < 4; kk++) {
            wmma::fragment<wmma::matrix_a, 16, 16, 16, __nv_bfloat16, wmma::row_major> ah[2], al[2];
            wmma::fragment<wmma::matrix_b, 16, 16, 16, __nv_bfloat16, wmma::col_major> bh[4], bl[4];
#pragma unroll
            for (int i = 0; i < 2; i++) {
                wmma::load_matrix_sync(ah[i], Ah + (wc * 32 + i * 16) * 72 + kk * 16, 72);
                wmma::load_matrix_sync(al[i], Al + (wc * 32 + i * 16) * 72 + kk * 16, 72);
            }
#pragma unroll
            for (int j = 0; j < 4; j++) {
                wmma::load_matrix_sync(bh[j], Bh + (wt * 64 + j * 16) * 72 + kk * 16, 72);
                wmma::load_matrix_sync(bl[j], Bl + (wt * 64 + j * 16) * 72 + kk * 16, 72);
            }
#pragma unroll
            for (int i = 0; i < 2; i++)
#pragma unroll
                for (int j = 0; j < 4; j++) {
                    wmma::mma_sync(c[i][j], ah[i], bh[j], c[i][j]);
                    wmma::mma_sync(c[i][j], ah[i], bl[j], c[i][j]);
                    wmma::mma_sync(c[i][j], al[i], bh[j], c[i][j]);
                }
        }
        __syncthreads();
    }
    float* ob = out + ((size_t)b * 512 + co0) * OUTP + t0;
#pragma unroll
    for (int i = 0; i < 2; i++)
#pragma unroll
        for (int j = 0; j < 4; j++)
            wmma::store_matrix_sync(ob + (size_t)(wc * 32 + i * 16) * OUTP + wt * 64 + j * 16,
                                    c[i][j], OUTP, wmma::mem_row_major);
}

// ---- stats / norm (stride-aware) ----
__global__ void zero_stats_k(double* stats) { if (threadIdx.x < 32) stats[threadIdx.x] = 0.0; }

__global__ void stats_k(const float* __restrict__ in, double* stats, int T, int TP) {
    __shared__ double s1[256], s2[256];
    int b = blockIdx.x;
    int L = 512 * T;
    int cs = (L + gridDim.y - 1) / gridDim.y;
    int start = blockIdx.y * cs, end = min(L, start + cs);
    const float* p = in + (size_t)b * 512 * TP;
    double s = 0.0, q = 0.0;
    for (int i = start + threadIdx.x; i < end; i += 256) {
        int c = i / T, t = i - c * T;
        double v = p[(size_t)c * TP + t];
        s += v; q += v * v;
    }
    s1[threadIdx.x] = s; s2[threadIdx.x] = q;
    __syncthreads();
    for (int st = 128; st > 0; st >>= 1) {
        if (threadIdx.x < st) { s1[threadIdx.x] += s1[threadIdx.x + st]; s2[threadIdx.x] += s2[threadIdx.x + st]; }
        __syncthreads();
    }
    if (threadIdx.x == 0) { atomicAdd(&stats[2 * b], s1[0]); atomicAdd(&stats[2 * b + 1], s2[0]); }
}

__global__ void statsfin_k(const double* stats, float2* murs, int L) {
    int i = threadIdx.x;
    if (i < NB) {
        double mu = stats[2 * i] / L;
        double var = stats[2 * i + 1] / L - mu * mu;
        murs[i] = make_float2((float)mu, (float)(1.0 / sqrt(var + 1e-5)));
    }
}

__global__ void normpack_k(const float* __restrict__ in, unsigned short* __restrict__ hip,
                           unsigned short* __restrict__ lop, const float* __restrict__ g,
                           const float* __restrict__ be, const float2* __restrict__ murs,
                           int T, int TP) {
    long long total = (long long)NB * CCH * T;
    long long idx = (long long)blockIdx.x * 256 + threadIdx.x;
    if (idx >= total) return;
    int b = (int)(idx / ((long long)CCH * T));
    long long rem = idx - (long long)b * CCH * T;
    int c = (int)(rem / T), t = (int)(rem - (long long)c * T);
    float2 mr = murs[b];
    size_t src = ((size_t)b * CCH + c) * TP + t;
    float v = fmaxf((in[src] - mr.x) * mr.y * g[c] + be[c], 0.f);
    __nv_bfloat16 h = __float2bfloat16(v);
    __nv_bfloat16 l = __float2bfloat16(v - __bfloat162float(h));
    hip[src] = __bfloat16_as_ushort(h);
    lop[src] = __bfloat16_as_ushort(l);
}

__global__ void norm_k(const float* __restrict__ buf, float* __restrict__ outp,
                       const float* __restrict__ g, const float* __restrict__ be,
                       const float2* __restrict__ murs, int T, int TP) {
    long long total = (long long)NB * CCH * T;
    long long idx = (long long)blockIdx.x * 256 + threadIdx.x;
    if (idx >= total) return;
    int b = (int)(idx / ((long long)CCH * T));
    long long rem = idx - (long long)b * CCH * T;
    int c = (int)(rem / T), t = (int)(rem - (long long)c * T);
    float2 mr = murs[b];
    outp[idx] = fmaxf((buf[((size_t)b * CCH + c) * TP + t] - mr.x) * mr.y * g[c] + be[c], 0.f);
}

// ---- features -> cost -> sinkhorn ----
__global__ void sqnorm_k(const float* __restrict__ f, float* __restrict__ s) {
    int idx = blockIdx.x * 256 + threadIdx.x;
    if (idx >= NB * CCH) return;
    const float* p = f + (size_t)idx * T4;
    float acc = 0.f;
    for (int d = 0; d < T4; d++) acc = fmaf(p[d], p[d], acc);
    s[idx] = acc;
}

__global__ __launch_bounds__(256) void cost_k(const float* __restrict__ A, const float* __restrict__ Bf,
                                              const float* __restrict__ sa, const float* __restrict__ sb,
                                              float* __restrict__ Co) {
    __shared__ float As[64][17], Bs[64][17];
    int b = blockIdx.z;
    const float* Ab = A + (size_t)b * 512 * T4;
    const float* Bb = Bf + (size_t)b * 512 * T4;
    int n0 = blockIdx.y * 64, m0 = blockIdx.x * 64;
    int tid = threadIdx.x, rn = tid >> 4, cm = tid & 15;
    float acc[4][4];
#pragma unroll
    for (int i = 0; i < 4; i++)
#pragma unroll
        for (int j = 0; j < 4; j++) acc[i][j] = 0.f;
    for (int d0 = 0; d0 < T4; d0 += 16) {
#pragma unroll
        for (int q = 0; q < 4; q++) {
            int e = tid + q * 256, r = e >> 4, dd = e & 15;
            As[r][dd] = (d0 + dd < T4) ? Ab[(size_t)(n0 + r) * T4 + d0 + dd] : 0.f;
            Bs[r][dd] = (d0 + dd < T4) ? Bb[(size_t)(m0 + r) * T4 + d0 + dd] : 0.f;
        }
        __syncthreads();
#pragma unroll
        for (int dd = 0; dd < 16; dd++) {
            float a[4], bb[4];
#pragma unroll
            for (int i = 0; i < 4; i++) a[i] = As[rn * 4 + i][dd];
#pragma unroll
            for (int j = 0; j < 4; j++) bb[j] = Bs[cm * 4 + j][dd];
#pragma unroll
            for (int i = 0; i < 4; i++)
#pragma unroll
                for (int j = 0; j < 4; j++) acc[i][j] = fmaf(a[i], bb[j], acc[i][j]);
        }
        __syncthreads();
    }
    const float* sab = sa + b * 512;
    const float* sbb = sb + b * 512;
    float* Cb = Co + (size_t)b * 512 * 512;
#pragma unroll
    for (int i = 0; i < 4; i++) {
        int n = n0 + rn * 4 + i;
#pragma unroll
        for (int j = 0; j < 4; j++) {
            int m = m0 + cm * 4 + j;
            Cb[(size_t)n * 512 + m] = 0.5f * fmaxf(sab[n] + sbb[m] - 2.f * acc[i][j], 0.f);
        }
    }
}

__global__ __launch_bounds__(512) void sinkhorn_k(const float* __restrict__ Cxy, const float* __restrict__ Cyx,
                                                  const float* __restrict__ Cxx, const float* __restrict__ Cyy,
                                                  float* __restrict__ w) {
    __shared__ float fs[512], gs[512];
    int b = blockIdx.x, ot = blockIdx.y;
    size_t off = (size_t)b * 512 * 512;
    const float *Cg, *Cf;
    if (ot == 0) { Cg = Cxy + off; Cf = Cyx + off; }
    else if (ot == 1) { Cg = Cxx + off; Cf = Cg; }
    else { Cg = Cyy + off; Cf = Cg; }
    int tid = threadIdx.x;
    fs[tid] = 0.f; gs[tid] = 0.f;
    __syncthreads();
    const float LA = -6.2383246250395075f, EPS = 0.0025f, IEPS = 400.f;
    for (int it = 0; it < 50; it++) {
        {
            const float* cp = Cg + tid;
            float M = -3.4e38f;
            for (int n = 0; n < 512; n += 8) {
                float v[8];
#pragma unroll
                for (int i = 0; i < 8; i++) v[i] = fs[n + i] - cp[(size_t)(n + i) << 9];
#pragma unroll
                for (int i = 0; i < 8; i++) M = fmaxf(M, v[i]);
            }
            float S = 0.f;
            for (int n = 0; n < 512; n += 8) {
                float v[8];
#pragma unroll
                for (int i = 0; i < 8; i++) v[i] = fs[n + i] - cp[(size_t)(n + i) << 9];
                float vm = v[0];
#pragma unroll
                for (int i = 1; i < 8; i++) vm = fmaxf(vm, v[i]);
                if (vm > M - 0.06f) {
#pragma unroll
                    for (int i = 0; i < 8; i++) S += __expf((v[i] - M) * IEPS);
                }
            }
            gs[tid] = -EPS * (LA + __logf(S)) - M;
        }
        __syncthreads();
        {
            const float* cp = Cf + tid;
            float M = -3.4e38f;
            for (int m = 0; m < 512; m += 8) {
                float v[8];
#pragma unroll
                for (int i = 0; i < 8; i++) v[i] = gs[m + i] - cp[(size_t)(m + i) << 9];
#pragma unroll
                for (int i = 0; i < 8; i++) M = fmaxf(M, v[i]);
            }
            float S = 0.f;
            for (int m = 0; m < 512; m += 8) {
                float v[8];
#pragma unroll
                for (int i = 0; i < 8; i++) v[i] = gs[m + i] - cp[(size_t)(m + i) << 9];
                float vm = v[0];
#pragma unroll
                for (int i = 1; i < 8; i++) vm = fmaxf(vm, v[i]);
                if (vm > M - 0.06f) {
#pragma unroll
                    for (int i = 0; i < 8; i++) S += __expf((v[i] - M) * IEPS);
                }
            }
            fs[tid] = -EPS * (LA + __logf(S)) - M;
        }
        __syncthreads();
    }
    fs[tid] += gs[tid];
    __syncthreads();
    for (int s = 256; s > 0; s >>= 1) {
        if (tid < s) fs[tid] += fs[tid + s];
        __syncthreads();
    }
    if (tid == 0) w[ot * 16 + b] = fs[0] * (1.f / 512.f);
}

__global__ void final_k(const float* __restrict__ w, float* __restrict__ out) {
    int b = threadIdx.x;
    if (b < NB) out[b] = w[b] - 0.5f * (w[16 + b] + w[32 + b]);
}

// ---- host driver ----
extern "C" void kernel_launch(void* const* d_in, const int* in_sizes, int n_in,
                              void* d_out, int out_size) {
    (void)out_size;
    const float* y_hat = (const float*)d_in[0];
    const float* y = (const float*)d_in[1];
    const float *W[5], *g[5], *be[5];
    if (n_in >= 17 && in_sizes[3] <= 1024) {
        for (int i = 0; i < 5; i++) {
            W[i] = (const float*)d_in[2 + 3 * i];
            g[i] = (const float*)d_in[3 + 3 * i];
            be[i] = (const float*)d_in[4 + 3 * i];
        }
    } else {
        for (int i = 0; i < 5; i++) {
            W[i] = (const float*)d_in[2 + i];
            g[i] = (const float*)d_in[7 + i];
            be[i] = (const float*)d_in[12 + i];
        }
    }
    float* out = (float*)d_out;

    float* pool; unsigned short* wb; double* stats; float2* murs; float* wv;
    cudaGetSymbolAddress((void**)&pool, d_pool);
    cudaGetSymbolAddress((void**)&wb, d_WB);
    cudaGetSymbolAddress((void**)&stats, d_stats);
    cudaGetSymbolAddress((void**)&murs, d_murs);
    cudaGetSymbolAddress((void**)&wv, d_w);

    unsigned short* PL = (unsigned short*)(pool + OFF_PL);
    float* OUT = pool + OFF_OUT;
    float* fx = pool + OFF_FX;
    float* fy = pool + OFF_FY;
    float* sx = pool + OFF_SX;
    float* sy = pool + OFF_SY;

    const int SMEM_W = 4 * 128 * 72 * 2;  // 73728
    cudaFuncSetAttribute(conv_wmma<8, 4>, cudaFuncAttributeMaxDynamicSharedMemorySize, SMEM_W);
    cudaFuncSetAttribute(conv_wmma<4, 2>, cudaFuncAttributeMaxDynamicSharedMemorySize, SMEM_W);

    packW_k<<<512 * 4096 / 256, 256>>>(W[1], wb + W1H, wb + W1L, 512 * 4096);
    packW_k<<<512 * 2048 / 256, 256>>>(W[2], wb + W2H, wb + W2L, 512 * 2048);
    packW_k<<<512 * 2048 / 256, 256>>>(W[3], wb + W3H, wb + W3L, 512 * 2048);
    packW_k<<<512 * 2048 / 256, 256>>>(W[4], wb + W4H, wb + W4L, 512 * 2048);

    for (int s = 0; s < 2; s++) {
        const float* wav = s ? y : y_hat;
        float* feat = s ? fy : fx;

        // layer 0
        unsigned short* h0 = PL;
        unsigned short* l0 = PL + (size_t)NB * 512 * T0P;
        zero_stats_k<<<1, 32>>>(stats);
        conv0_stats_k<<<dim3((T0 + 127) / 128, NB), 128>>>(wav, W[0], stats);
        statsfin_k<<<1, 32>>>(stats, murs, 512 * T0);
        conv0_pack_k<<<dim3((T0 + 127) / 128, NB), 128>>>(wav, W[0], g[0], be[0], murs, h0, l0);

        // layer 1
        conv_wmma<8, 4><<<dim3(O1P / 128, 4, NB), 256, SMEM_W>>>(h0, l0, wb + W1H, wb + W1L,
                                                                 OUT, T0P, O1P, T1, 4096);
        zero_stats_k<<<1, 32>>>(stats);
        stats_k<<<dim3(16, 48), 256>>>(OUT, stats, T1, O1P);
        statsfin_k<<<1, 32>>>(stats, murs, 512 * T1);
        unsigned short* h1 = PL;
        unsigned short* l1 = PL + (size_t)NB * 512 * O1P;
        normpack_k<<<(unsigned)(((long long)NB * CCH * T1 + 255) / 256), 256>>>(OUT, h1, l1, g[1], be[1], murs, T1, O1P);

        // layer 2
        conv_wmma<4, 2><<<dim3(O2P / 128, 4, NB), 256, SMEM_W>>>(h1, l1, wb + W2H, wb + W2L,
                                                                 OUT, O1P, O2P, T2, 2048);
        zero_stats_k<<<1, 32>>>(stats);
        stats_k<<<dim3(16, 48), 256>>>(OUT, stats, T2, O2P);
        statsfin_k<<<1, 32>>>(stats, murs, 512 * T2);
        unsigned short* h2 = PL;
        unsigned short* l2 = PL + (size_t)NB * 512 * O2P;
        normpack_k<<<(unsigned)(((long long)NB * CCH * T2 + 255) / 256), 256>>>(OUT, h2, l2, g[2], be[2], murs, T2, O2P);

        // layer 3
        conv_wmma<4, 2><<<dim3(O3P / 128, 4, NB), 256, SMEM_W>>>(h2, l2, wb + W3H, wb + W3L,
                                                                 OUT, O2P, O3P, T3, 2048);
        zero_stats_k<<<1, 32>>>(stats);
        stats_k<<<dim3(16, 48), 256>>>(OUT, stats, T3, O3P);
        statsfin_k<<<1, 32>>>(stats, murs, 512 * T3);
        unsigned short* h3 = PL;
        unsigned short* l3 = PL + (size_t)NB * 512 * O3P;
        normpack_k<<<(unsigned)(((long long)NB * CCH * T3 + 255) / 256), 256>>>(OUT, h3, l3, g[3], be[3], murs, T3, O3P);

        // layer 4
        conv_wmma<4, 2><<<dim3(O4P / 128, 4, NB), 256, SMEM_W>>>(h3, l3, wb + W4H, wb + W4L,
                                                                 OUT, O3P, O4P, T4, 2048);
        zero_stats_k<<<1, 32>>>(stats);
        stats_k<<<dim3(16, 48), 256>>>(OUT, stats, T4, O4P);
        statsfin_k<<<1, 32>>>(stats, murs, 512 * T4);
        norm_k<<<(unsigned)(((long long)NB * CCH * T4 + 255) / 256), 256>>>(OUT, feat, g[4], be[4], murs, T4, O4P);
    }

    sqnorm_k<<<(NB * CCH + 255) / 256, 256>>>(fx, sx);
    sqnorm_k<<<(NB * CCH + 255) / 256, 256>>>(fy, sy);

    float* Cxy = pool + OFF_CXY;
    float* Cyx = pool + OFF_CYX;
    float* Cxx = pool + OFF_CXX;
    float* Cyy = pool + OFF_CYY;
    cost_k<<<dim3(8, 8, NB), 256>>>(fx, fy, sx, sy, Cxy);
    cost_k<<<dim3(8, 8, NB), 256>>>(fy, fx, sy, sx, Cyx);
    cost_k<<<dim3(8, 8, NB), 256>>>(fx, fx, sx, sx, Cxx);
    cost_k<<<dim3(8, 8, NB), 256>>>(fy, fy, sy, sy, Cyy);

    sinkhorn_k<<<dim3(NB, 3), 512>>>(Cxy, Cyx, Cxx, Cyy, wv);
    final_k<<<1, 32>>>(wv, out);
}

// round 12
// speedup vs baseline: 1.8259x; 1.0461x over previous
#include <cuda_runtime.h>
#include <cuda_bf16.h>
#include <mma.h>
#include <math.h>
#include <stdint.h>

using namespace nvcuda;

#define NB 16
#define CCH 512
#define T0 6399
#define T1 1598
#define T2 798
#define T3 398
#define T4 198
#define T0P 6400
#define O1P 1664
#define O2P 896
#define O3P 512
#define O4P 256

#define PL_ELEMS  ((size_t)NB * 512 * T0P)
#define OUT_ELEMS ((size_t)NB * 512 * O1P)
#define F_ELEMS   ((size_t)NB * 512 * T4)
#define C_ELEMS   ((size_t)NB * 512 * 512)
#define OFF_PL   ((size_t)0)
#define OFF_OUT  (OFF_PL + PL_ELEMS + 1024)
#define OFF_FX   (OFF_OUT + OUT_ELEMS + 1024)
#define OFF_FY   (OFF_FX + F_ELEMS)
#define OFF_SX   (OFF_FY + F_ELEMS)
#define OFF_SY   (OFF_SX + NB * CCH)
#define POOL_TOTAL (OFF_SY + NB * CCH + 1024)
#define OFF_CXY  (OFF_PL)
#define OFF_CYX  (OFF_CXY + C_ELEMS)
#define OFF_CXX  (OFF_CYX + C_ELEMS)
#define OFF_CYY  (OFF_CXX + C_ELEMS)

__device__ float d_pool[POOL_TOTAL];
__device__ unsigned short d_WB[2 * 512 * 4096 + 6 * 512 * 2048];
__device__ double d_stats[2 * NB];
__device__ float2 d_murs[NB];
__device__ float d_w[3 * NB];
#define W1H ((size_t)0)
#define W1L (W1H + (size_t)512 * 4096)
#define W2H (W1L + (size_t)512 * 4096)
#define W2L (W2H + (size_t)512 * 2048)
#define W3H (W2L + (size_t)512 * 2048)
#define W3L (W3H + (size_t)512 * 2048)
#define W4H (W3L + (size_t)512 * 2048)
#define W4L (W4H + (size_t)512 * 2048)

// ---- cp.async helpers (size must match BOTH global and shared alignment) ----
__device__ __forceinline__ uint32_t smem_u32(const void* p) {
    uint32_t a;
    asm("{ .reg .u64 t; cvta.to.shared.u64 t, %1; cvt.u32.u64 %0, t; }" : "=r"(a) : "l"(p));
    return a;
}
__device__ __forceinline__ void cpa16(void* s, const void* g) {
    asm volatile("cp.async.cg.shared.global [%0], [%1], 16;" :: "r"(smem_u32(s)), "l"(g));
}
__device__ __forceinline__ void cpa8(void* s, const void* g) {
    asm volatile("cp.async.ca.shared.global [%0], [%1], 8;" :: "r"(smem_u32(s)), "l"(g));
}
__device__ __forceinline__ void cpa4(void* s, const void* g) {
    asm volatile("cp.async.ca.shared.global [%0], [%1], 4;" :: "r"(smem_u32(s)), "l"(g));
}
#define CP_COMMIT() asm volatile("cp.async.commit_group;" ::: "memory")
#define CP_WAIT1() asm volatile("cp.async.wait_group 1;" ::: "memory")
#define CP_WAIT0() asm volatile("cp.async.wait_group 0;" ::: "memory")

// ---- single-launch weight pack ----
__global__ void packAll_k(const float* __restrict__ W1, const float* __restrict__ W2,
                          const float* __restrict__ W3, const float* __restrict__ W4,
                          unsigned short* __restrict__ wb) {
    const int S1 = 512 * 4096, S2 = 512 * 2048;
    int e = blockIdx.x * 256 + threadIdx.x;
    const float* src;
    size_t ho, lo_;
    int off;
    if (e < S1) { src = W1; off = e; ho = W1H; lo_ = W1L; }
    else {
        int r = e - S1;
        int seg = r / S2;
        off = r - seg * S2;
        if (seg == 0) { src = W2; ho = W2H; lo_ = W2L; }
        else if (seg == 1) { src = W3; ho = W3H; lo_ = W3L; }
        else { src = W4; ho = W4H; lo_ = W4L; }
    }
    float x = src[off];
    __nv_bfloat16 h = __float2bfloat16(x);
    __nv_bfloat16 l = __float2bfloat16(x - __bfloat162float(h));
    wb[ho + off] = __bfloat16_as_ushort(h);
    wb[lo_ + off] = __bfloat16_as_ushort(l);
}

// ---- conv0 (cin=1,k=10,s=5): stats + fused norm/pack ----
__global__ void conv0_stats_k(const float* __restrict__ wav, const float* __restrict__ W0,
                              double* stats) {
    __shared__ float Ws[5120];
    __shared__ double r1[128], r2[128];
    int tid = threadIdx.x;
    for (int e = tid; e < 5120; e += 128) Ws[e] = W0[e];
    __syncthreads();
    int b = blockIdx.y, t = blockIdx.x * 128 + tid;
    double s = 0.0, q = 0.0;
    if (t < T0) {
        float w[10];
        const float* wp = wav + (size_t)b * 32000 + t * 5;
#pragma unroll
        for (int j = 0; j < 10; j++) w[j] = wp[j];
        for (int co = 0; co < 512; co++) {
            float a = 0.f;
#pragma unroll
            for (int j = 0; j < 10; j++) a = fmaf(Ws[co * 10 + j], w[j], a);
            s += a; q += (double)a * a;
        }
    }
    r1[tid] = s; r2[tid] = q;
    __syncthreads();
    for (int st = 64; st > 0; st >>= 1) {
        if (tid < st) { r1[tid] += r1[tid + st]; r2[tid] += r2[tid + st]; }
        __syncthreads();
    }
    if (tid == 0) { atomicAdd(&stats[2 * b], r1[0]); atomicAdd(&stats[2 * b + 1], r2[0]); }
}

__global__ void conv0_pack_k(const float* __restrict__ wav, const float* __restrict__ W0,
                             const float* __restrict__ g, const float* __restrict__ be,
                             const float2* __restrict__ murs,
                             unsigned short* __restrict__ hip, unsigned short* __restrict__ lop) {
    __shared__ float Ws[5120], gS[512], bS[512];
    int tid = threadIdx.x;
    for (int e = tid; e < 5120; e += 128) Ws[e] = W0[e];
    for (int e = tid; e < 512; e += 128) { gS[e] = g[e]; bS[e] = be[e]; }
    __syncthreads();
    int b = blockIdx.y, t = blockIdx.x * 128 + tid;
    if (t >= T0) return;
    float2 mr = murs[b];
    float w[10];
    const float* wp = wav + (size_t)b * 32000 + t * 5;
#pragma unroll
    for (int j = 0; j < 10; j++) w[j] = wp[j];
    size_t base = (size_t)b * 512 * T0P + t;
    for (int co = 0; co < 512; co++) {
        float a = 0.f;
#pragma unroll
        for (int j = 0; j < 10; j++) a = fmaf(Ws[co * 10 + j], w[j], a);
        float v = fmaxf((a - mr.x) * mr.y * gS[co] + bS[co], 0.f);
        __nv_bfloat16 h = __float2bfloat16(v);
        __nv_bfloat16 l = __float2bfloat16(v - __bfloat162float(h));
        hip[base + (size_t)co * T0P] = __bfloat16_as_ushort(h);
        lop[base + (size_t)co * T0P] = __bfloat16_as_ushort(l);
    }
}

// ---- WMMA conv GEMM: 128co x 128t, K-chunk 32, cp.async double-buffered ----
#define CHW 40  // 32 + 8 pad -> 80B row
template <int KW, int SS>
__global__ __launch_bounds__(256) void conv_wmma(
    const unsigned short* __restrict__ hiP, const unsigned short* __restrict__ loP,
    const unsigned short* __restrict__ Whp, const unsigned short* __restrict__ Wlp,
    float* __restrict__ out, int TPin, int OUTP, int Tout, int K) {
    extern __shared__ char smem[];
    const int PLN = 128 * CHW;
    __nv_bfloat16* bufs = (__nv_bfloat16*)smem;
    int tid = threadIdx.x, wid = tid >> 5;
    int wc = wid & 3, wt = wid >> 2;
    int t0 = blockIdx.x * 128, co0 = blockIdx.y * 128, b = blockIdx.z;
    const unsigned short* hB = hiP + (size_t)b * 512 * TPin;
    const unsigned short* lB = loP + (size_t)b * 512 * TPin;

    wmma::fragment<wmma::accumulator, 16, 16, 16, float> c[2][4];
#pragma unroll
    for (int i = 0; i < 2; i++)
#pragma unroll
        for (int j = 0; j < 4; j++) wmma::fill_fragment(c[i][j], 0.0f);

    int KC = K >> 5;

    auto fill = [&](__nv_bfloat16* bf, int ch) {
        int kb = ch << 5;
        __nv_bfloat16* Ah = bf;
        __nv_bfloat16* Al = bf + PLN;
        __nv_bfloat16* Bh = bf + 2 * PLN;
        __nv_bfloat16* Bl = bf + 3 * PLN;
        {   // A: 16B-aligned both sides
            int row = tid >> 1, half = tid & 1;
            const unsigned short* gh = Whp + (size_t)(co0 + row) * K + kb + half * 16;
            const unsigned short* gl = Wlp + (size_t)(co0 + row) * K + kb + half * 16;
            __nv_bfloat16* dh = Ah + row * CHW + half * 16;
            __nv_bfloat16* dl = Al + row * CHW + half * 16;
            cpa16(dh, gh); cpa16(dh + 8, gh + 8);
            cpa16(dl, gl); cpa16(dl + 8, gl + 8);
        }
        if (KW == 8) {  // global byte offset 8*tt -> 8B aligned: use cpa8
#pragma unroll
            for (int r = 0; r < 2; r++) {
                int e = r * 256 + tid;
                int t = e & 127, cc = e >> 7;
                int tt = t0 + t; if (tt > Tout - 1) tt = Tout - 1;
                size_t s = (size_t)((kb >> 3) + cc) * TPin + (size_t)tt * SS;
                __nv_bfloat16* dh = Bh + t * CHW + cc * 8;
                __nv_bfloat16* dl = Bl + t * CHW + cc * 8;
                cpa8(dh, hB + s); cpa8(dh + 4, hB + s + 4);
                cpa8(dl, lB + s); cpa8(dl + 4, lB + s + 4);
            }
        } else {  // global byte offset 4*tt -> 4B aligned: use cpa4
#pragma unroll
            for (int r = 0; r < 4; r++) {
                int e = r * 256 + tid;
                int t = e & 127, cc = e >> 7;
                int tt = t0 + t; if (tt > Tout - 1) tt = Tout - 1;
                size_t s = (size_t)((kb >> 2) + cc) * TPin + (size_t)tt * SS;
                __nv_bfloat16* dh = Bh + t * CHW + cc * 4;
                __nv_bfloat16* dl = Bl + t * CHW + cc * 4;
                cpa4(dh, hB + s); cpa4(dh + 2, hB + s + 2);
                cpa4(dl, lB + s); cpa4(dl + 2, lB + s + 2);
            }
        }
    };

    fill(bufs, 0);
    CP_COMMIT();
    for (int ch = 0; ch < KC; ch++) {
        __nv_bfloat16* cur = bufs + (ch & 1) * 4 * PLN;
        __nv_bfloat16* nxt = bufs + ((ch + 1) & 1) * 4 * PLN;
        if (ch + 1 < KC) { fill(nxt, ch + 1); CP_COMMIT(); CP_WAIT1(); }
        else CP_WAIT0();
        __syncthreads();
        __nv_bfloat16* Ah = cur;
        __nv_bfloat16* Al = cur + PLN;
        __nv_bfloat16* Bh = cur + 2 * PLN;
        __nv_bfloat16* Bl = cur + 3 * PLN;
#pragma unroll
        for (int kk = 0; kk < 2; kk++) {
            wmma::fragment<wmma::matrix_a, 16, 16, 16, __nv_bfloat16, wmma::row_major> ah[2], al[2];
#pragma unroll
            for (int i = 0; i < 2; i++) {
                wmma::load_matrix_sync(ah[i], Ah + (wc * 32 + i * 16) * CHW + kk * 16, CHW);
                wmma::load_matrix_sync(al[i], Al + (wc * 32 + i * 16) * CHW + kk * 16, CHW);
            }
#pragma unroll
            for (int j = 0; j < 4; j++) {
                wmma::fragment<wmma::matrix_b, 16, 16, 16, __nv_bfloat16, wmma::col_major> bh, bl;
                wmma::load_matrix_sync(bh, Bh + (wt * 64 + j * 16) * CHW + kk * 16, CHW);
                wmma::load_matrix_sync(bl, Bl + (wt * 64 + j * 16) * CHW + kk * 16, CHW);
#pragma unroll
                for (int i = 0; i < 2; i++) {
                    wmma::mma_sync(c[i][j], ah[i], bh, c[i][j]);
                    wmma::mma_sync(c[i][j], ah[i], bl, c[i][j]);
                    wmma::mma_sync(c[i][j], al[i], bh, c[i][j]);
                }
            }
        }
        __syncthreads();
    }
    float* ob = out + ((size_t)b * 512 + co0) * OUTP + t0;
#pragma unroll
    for (int i = 0; i < 2; i++)
#pragma unroll
        for (int j = 0; j < 4; j++)
            wmma::store_matrix_sync(ob + (size_t)(wc * 32 + i * 16) * OUTP + wt * 64 + j * 16,
                                    c[i][j], OUTP, wmma::mem_row_major);
}

// ---- stats / norm (stride-aware) ----
__global__ void zero_stats_k(double* stats) { if (threadIdx.x < 32) stats[threadIdx.x] = 0.0; }

__global__ void stats_k(const float* __restrict__ in, double* stats, int T, int TP) {
    __shared__ double s1[256], s2[256];
    int b = blockIdx.x;
    int L = 512 * T;
    int cs = (L + gridDim.y - 1) / gridDim.y;
    int start = blockIdx.y * cs, end = min(L, start + cs);
    const float* p = in + (size_t)b * 512 * TP;
    double s = 0.0, q = 0.0;
    for (int i = start + threadIdx.x; i < end; i += 256) {
        int c = i / T, t = i - c * T;
        double v = p[(size_t)c * TP + t];
        s += v; q += v * v;
    }
    s1[threadIdx.x] = s; s2[threadIdx.x] = q;
    __syncthreads();
    for (int st = 128; st > 0; st >>= 1) {
        if (threadIdx.x < st) { s1[threadIdx.x] += s1[threadIdx.x + st]; s2[threadIdx.x] += s2[threadIdx.x + st]; }
        __syncthreads();
    }
    if (threadIdx.x == 0) { atomicAdd(&stats[2 * b], s1[0]); atomicAdd(&stats[2 * b + 1], s2[0]); }
}

__global__ void statsfin_k(const double* stats, float2* murs, int L) {
    int i = threadIdx.x;
    if (i < NB) {
        double mu = stats[2 * i] / L;
        double var = stats[2 * i + 1] / L - mu * mu;
        murs[i] = make_float2((float)mu, (float)(1.0 / sqrt(var + 1e-5)));
    }
}

__global__ void normpack_k(const float* __restrict__ in, unsigned short* __restrict__ hip,
                           unsigned short* __restrict__ lop, const float* __restrict__ g,
                           const float* __restrict__ be, const float2* __restrict__ murs,
                           int T, int TP) {
    long long total = (long long)NB * CCH * T;
    long long idx = (long long)blockIdx.x * 256 + threadIdx.x;
    if (idx >= total) return;
    int b = (int)(idx / ((long long)CCH * T));
    long long rem = idx - (long long)b * CCH * T;
    int c = (int)(rem / T), t = (int)(rem - (long long)c * T);
    float2 mr = murs[b];
    size_t src = ((size_t)b * CCH + c) * TP + t;
    float v = fmaxf((in[src] - mr.x) * mr.y * g[c] + be[c], 0.f);
    __nv_bfloat16 h = __float2bfloat16(v);
    __nv_bfloat16 l = __float2bfloat16(v - __bfloat162float(h));
    hip[src] = __bfloat16_as_ushort(h);
    lop[src] = __bfloat16_as_ushort(l);
}

__global__ void norm_k(const float* __restrict__ buf, float* __restrict__ outp,
                       const float* __restrict__ g, const float* __restrict__ be,
                       const float2* __restrict__ murs, int T, int TP) {
    long long total = (long long)NB * CCH * T;
    long long idx = (long long)blockIdx.x * 256 + threadIdx.x;
    if (idx >= total) return;
    int b = (int)(idx / ((long long)CCH * T));
    long long rem = idx - (long long)b * CCH * T;
    int c = (int)(rem / T), t = (int)(rem - (long long)c * T);
    float2 mr = murs[b];
    outp[idx] = fmaxf((buf[((size_t)b * CCH + c) * TP + t] - mr.x) * mr.y * g[c] + be[c], 0.f);
}

// ---- features -> cost -> sinkhorn ----
__global__ void sqnorm_k(const float* __restrict__ f, float* __restrict__ s) {
    int idx = blockIdx.x * 256 + threadIdx.x;
    if (idx >= NB * CCH) return;
    const float* p = f + (size_t)idx * T4;
    float acc = 0.f;
    for (int d = 0; d < T4; d++) acc = fmaf(p[d], p[d], acc);
    s[idx] = acc;
}

__global__ __launch_bounds__(256) void cost_k(const float* __restrict__ A, const float* __restrict__ Bf,
                                              const float* __restrict__ sa, const float* __restrict__ sb,
                                              float* __restrict__ Co) {
    __shared__ float As[64][17], Bs[64][17];
    int b = blockIdx.z;
    const float* Ab = A + (size_t)b * 512 * T4;
    const float* Bb = Bf + (size_t)b * 512 * T4;
    int n0 = blockIdx.y * 64, m0 = blockIdx.x * 64;
    int tid = threadIdx.x, rn = tid >> 4, cm = tid & 15;
    float acc[4][4];
#pragma unroll
    for (int i = 0; i < 4; i++)
#pragma unroll
        for (int j = 0; j < 4; j++) acc[i][j] = 0.f;
    for (int d0 = 0; d0 < T4; d0 += 16) {
#pragma unroll
        for (int q = 0; q < 4; q++) {
            int e = tid + q * 256, r = e >> 4, dd = e & 15;
            As[r][dd] = (d0 + dd < T4) ? Ab[(size_t)(n0 + r) * T4 + d0 + dd] : 0.f;
            Bs[r][dd] = (d0 + dd < T4) ? Bb[(size_t)(m0 + r) * T4 + d0 + dd] : 0.f;
        }
        __syncthreads();
#pragma unroll
        for (int dd = 0; dd < 16; dd++) {
            float a[4], bb[4];
#pragma unroll
            for (int i = 0; i < 4; i++) a[i] = As[rn * 4 + i][dd];
#pragma unroll
            for (int j = 0; j < 4; j++) bb[j] = Bs[cm * 4 + j][dd];
#pragma unroll
            for (int i = 0; i < 4; i++)
#pragma unroll
                for (int j = 0; j < 4; j++) acc[i][j] = fmaf(a[i], bb[j], acc[i][j]);
        }
        __syncthreads();
    }
    const float* sab = sa + b * 512;
    const float* sbb = sb + b * 512;
    float* Cb = Co + (size_t)b * 512 * 512;
#pragma unroll
    for (int i = 0; i < 4; i++) {
        int n = n0 + rn * 4 + i;
#pragma unroll
        for (int j = 0; j < 4; j++) {
            int m = m0 + cm * 4 + j;
            Cb[(size_t)n * 512 + m] = 0.5f * fmaxf(sab[n] + sbb[m] - 2.f * acc[i][j], 0.f);
        }
    }
}

// one-pass online log-domain LSE update
__device__ __forceinline__ float lse_update(const float* cp, const float* pot) {
    const float IEPS = 400.f;
    float M = -3.4e38f, S = 0.f;
    for (int n = 0; n < 512; n += 8) {
        float v[8];
#pragma unroll
        for (int i = 0; i < 8; i++) v[i] = pot[n + i] - cp[(size_t)(n + i) << 9];
        float vm = v[0];
#pragma unroll
        for (int i = 1; i < 8; i++) vm = fmaxf(vm, v[i]);
        if (vm > M) {
            S *= __expf((M - vm) * IEPS);
            M = vm;
#pragma unroll
            for (int i = 0; i < 8; i++) S += __expf((v[i] - M) * IEPS);
        } else if (vm > M - 0.06f) {
#pragma unroll
            for (int i = 0; i < 8; i++) S += __expf((v[i] - M) * IEPS);
        }
    }
    const float LA = -6.2383246250395075f, EPS = 0.0025f;
    return -EPS * (LA + __logf(S)) - M;
}

__global__ __launch_bounds__(512) void sinkhorn_k(const float* __restrict__ Cxy, const float* __restrict__ Cyx,
                                                  const float* __restrict__ Cxx, const float* __restrict__ Cyy,
                                                  float* __restrict__ w) {
    __shared__ float fs[512], gs[512];
    int b = blockIdx.x, ot = blockIdx.y;
    size_t off = (size_t)b * 512 * 512;
    const float *Cg, *Cf;
    if (ot == 0) { Cg = Cxy + off; Cf = Cyx + off; }
    else if (ot == 1) { Cg = Cxx + off; Cf = Cg; }
    else { Cg = Cyy + off; Cf = Cg; }
    int tid = threadIdx.x;
    fs[tid] = 0.f; gs[tid] = 0.f;
    __syncthreads();
    for (int it = 0; it < 50; it++) {
        gs[tid] = lse_update(Cg + tid, fs);
        __syncthreads();
        fs[tid] = lse_update(Cf + tid, gs);
        __syncthreads();
    }
    fs[tid] += gs[tid];
    __syncthreads();
    for (int s = 256; s > 0; s >>= 1) {
        if (tid < s) fs[tid] += fs[tid + s];
        __syncthreads();
    }
    if (tid == 0) w[ot * 16 + b] = fs[0] * (1.f / 512.f);
}

__global__ void final_k(const float* __restrict__ w, float* __restrict__ out) {
    int b = threadIdx.x;
    if (b < NB) out[b] = w[b] - 0.5f * (w[16 + b] + w[32 + b]);
}

// ---- host driver ----
extern "C" void kernel_launch(void* const* d_in, const int* in_sizes, int n_in,
                              void* d_out, int out_size) {
    (void)out_size;
    const float* y_hat = (const float*)d_in[0];
    const float* y = (const float*)d_in[1];
    const float *W[5], *g[5], *be[5];
    if (n_in >= 17 && in_sizes[3] <= 1024) {
        for (int i = 0; i < 5; i++) {
            W[i] = (const float*)d_in[2 + 3 * i];
            g[i] = (const float*)d_in[3 + 3 * i];
            be[i] = (const float*)d_in[4 + 3 * i];
        }
    } else {
        for (int i = 0; i < 5; i++) {
            W[i] = (const float*)d_in[2 + i];
            g[i] = (const float*)d_in[7 + i];
            be[i] = (const float*)d_in[12 + i];
        }
    }
    float* out = (float*)d_out;

    float* pool; unsigned short* wb; double* stats; float2* murs; float* wv;
    cudaGetSymbolAddress((void**)&pool, d_pool);
    cudaGetSymbolAddress((void**)&wb, d_WB);
    cudaGetSymbolAddress((void**)&stats, d_stats);
    cudaGetSymbolAddress((void**)&murs, d_murs);
    cudaGetSymbolAddress((void**)&wv, d_w);

    unsigned short* PL = (unsigned short*)(pool + OFF_PL);
    float* OUT = pool + OFF_OUT;
    float* fx = pool + OFF_FX;
    float* fy = pool + OFF_FY;
    float* sx = pool + OFF_SX;
    float* sy = pool + OFF_SY;

    const int SMEM_W = 2 * 4 * 128 * CHW * 2;  // 81920
    cudaFuncSetAttribute(conv_wmma<8, 4>, cudaFuncAttributeMaxDynamicSharedMemorySize, SMEM_W);
    cudaFuncSetAttribute(conv_wmma<4, 2>, cudaFuncAttributeMaxDynamicSharedMemorySize, SMEM_W);

    packAll_k<<<(512 * 4096 + 3 * 512 * 2048) / 256, 256>>>(W[1], W[2], W[3], W[4], wb);

    for (int s = 0; s < 2; s++) {
        const float* wav = s ? y : y_hat;
        float* feat = s ? fy : fx;

        unsigned short* h0 = PL;
        unsigned short* l0 = PL + (size_t)NB * 512 * T0P;
        zero_stats_k<<<1, 32>>>(stats);
        conv0_stats_k<<<dim3((T0 + 127) / 128, NB), 128>>>(wav, W[0], stats);
        statsfin_k<<<1, 32>>>(stats, murs, 512 * T0);
        conv0_pack_k<<<dim3((T0 + 127) / 128, NB), 128>>>(wav, W[0], g[0], be[0], murs, h0, l0);

        conv_wmma<8, 4><<<dim3(O1P / 128, 4, NB), 256, SMEM_W>>>(h0, l0, wb + W1H, wb + W1L,
                                                                 OUT, T0P, O1P, T1, 4096);
        zero_stats_k<<<1, 32>>>(stats);
        stats_k<<<dim3(16, 48), 256>>>(OUT, stats, T1, O1P);
        statsfin_k<<<1, 32>>>(stats, murs, 512 * T1);
        unsigned short* h1 = PL;
        unsigned short* l1 = PL + (size_t)NB * 512 * O1P;
        normpack_k<<<(unsigned)(((long long)NB * CCH * T1 + 255) / 256), 256>>>(OUT, h1, l1, g[1], be[1], murs, T1, O1P);

        conv_wmma<4, 2><<<dim3(O2P / 128, 4, NB), 256, SMEM_W>>>(h1, l1, wb + W2H, wb + W2L,
                                                                 OUT, O1P, O2P, T2, 2048);
        zero_stats_k<<<1, 32>>>(stats);
        stats_k<<<dim3(16, 48), 256>>>(OUT, stats, T2, O2P);
        statsfin_k<<<1, 32>>>(stats, murs, 512 * T2);
        unsigned short* h2 = PL;
        unsigned short* l2 = PL + (size_t)NB * 512 * O2P;
        normpack_k<<<(unsigned)(((long long)NB * CCH * T2 + 255) / 256), 256>>>(OUT, h2, l2, g[2], be[2], murs, T2, O2P);

        conv_wmma<4, 2><<<dim3(O3P / 128, 4, NB), 256, SMEM_W>>>(h2, l2, wb + W3H, wb + W3L,
                                                                 OUT, O2P, O3P, T3, 2048);
        zero_stats_k<<<1, 32>>>(stats);
        stats_k<<<dim3(16, 48), 256>>>(OUT, stats, T3, O3P);
        statsfin_k<<<1, 32>>>(stats, murs, 512 * T3);
        unsigned short* h3 = PL;
        unsigned short* l3 = PL + (size_t)NB * 512 * O3P;
        normpack_k<<<(unsigned)(((long long)NB * CCH * T3 + 255) / 256), 256>>>(OUT, h3, l3, g[3], be[3], murs, T3, O3P);

        conv_wmma<4, 2><<<dim3(O4P / 128, 4, NB), 256, SMEM_W>>>(h3, l3, wb + W4H, wb + W4L,
                                                                 OUT, O3P, O4P, T4, 2048);
        zero_stats_k<<<1, 32>>>(stats);
        stats_k<<<dim3(16, 48), 256>>>(OUT, stats, T4, O4P);
        statsfin_k<<<1, 32>>>(stats, murs, 512 * T4);
        norm_k<<<(unsigned)(((long long)NB * CCH * T4 + 255) / 256), 256>>>(OUT, feat, g[4], be[4], murs, T4, O4P);
    }

    sqnorm_k<<<(NB * CCH + 255) / 256, 256>>>(fx, sx);
    sqnorm_k<<<(NB * CCH + 255) / 256, 256>>>(fy, sy);

    float* Cxy = pool + OFF_CXY;
    float* Cyx = pool + OFF_CYX;
    float* Cxx = pool + OFF_CXX;
    float* Cyy = pool + OFF_CYY;
    cost_k<<<dim3(8, 8, NB), 256>>>(fx, fy, sx, sy, Cxy);
    cost_k<<<dim3(8, 8, NB), 256>>>(fy, fx, sy, sx, Cyx);
    cost_k<<<dim3(8, 8, NB), 256>>>(fx, fx, sx, sx, Cxx);
    cost_k<<<dim3(8, 8, NB), 256>>>(fy, fy, sy, sy, Cyy);

    sinkhorn_k<<<dim3(NB, 3), 512>>>(Cxy, Cyx, Cxx, Cyy, wv);
    final_k<<<1, 32>>>(wv, out);
}